// round 12
// baseline (speedup 1.0000x reference)
#include <cuda_runtime.h>
#include <cuda_fp16.h>
#include <cstdint>

// ---------------- problem constants ----------------
#define Bn 2
#define Sn 2048
#define Dn 1024
#define Vn 32000
#define NHEADS 8
#define DHn 128
#define DFFn 4096
#define Rn (Bn*Sn)   // 4096 total rows

// ---------------- fp32 scratch ----------------
__device__ float g_Xc[Rn*Dn];
__device__ float g_qkv[Rn*3*Dn];
__device__ float g_attno[Rn*Dn];
__device__ float g_x1[Rn*Dn];
__device__ float g_ff[Rn*Dn];
__device__ float g_x2[Rn*Dn];
__device__ float g_eff[Rn];
__device__ int   g_tidx[Rn];
__device__ int   g_tcnt[Bn];

// ---------------- fp16 planes ---------------------------------
__device__ __align__(16) __half g_Xc_h[Rn*Dn];
__device__ __align__(16) __half g_ctx_h[Rn*Dn];
__device__ __align__(16) __half g_x1_h[Rn*Dn];
__device__ __align__(16) __half g_hff_h[Rn*DFFn];
__device__ __align__(16) __half g_cat_h[Rn*2*Dn];
__device__ __align__(16) __half g_mix_h[Rn*Dn];
__device__ __align__(16) __half g_Wqkv_h[3*Dn*Dn];
__device__ __align__(16) __half g_Wo_h[Dn*Dn];
__device__ __align__(16) __half g_W1_h[DFFn*Dn];
__device__ __align__(16) __half g_W2_h[Dn*DFFn];
__device__ __align__(16) __half g_Wm_h[Dn*2*Dn];
__device__ __align__(16) __half g_Wout_h[Vn*Dn];

// ---------------- helpers -------------------------------------------------------
__device__ __forceinline__ uint32_t smem_u32(const void* p) {
    uint32_t a;
    asm("{ .reg .u64 t; cvta.to.shared.u64 t, %1; cvt.u32.u64 %0, t; }" : "=r"(a) : "l"(p));
    return a;
}
__device__ __forceinline__ uint32_t pk2h(__half a, __half b) {
    return ((uint32_t)__half_as_ushort(b) << 16) | (uint32_t)__half_as_ushort(a);
}
__device__ __forceinline__ uint2 cvt4h(float4 v) {
    uint2 h;
    h.x = pk2h(__float2half_rn(v.x), __float2half_rn(v.y));
    h.y = pk2h(__float2half_rn(v.z), __float2half_rn(v.w));
    return h;
}
__device__ __forceinline__ void cpa16(uint32_t dst, const void* src) {
    asm volatile("cp.async.cg.shared.global [%0], [%1], 16;" :: "r"(dst), "l"(src));
}
__device__ __forceinline__ void cp_commit() {
    asm volatile("cp.async.commit_group;" ::: "memory");
}
template<int N>
__device__ __forceinline__ void cp_wait() {
    asm volatile("cp.async.wait_group %0;" :: "n"(N) : "memory");
}
__device__ __forceinline__ void ldm4(uint32_t addr, uint32_t* r) {
    asm volatile("ldmatrix.sync.aligned.m8n8.x4.shared.b16 {%0,%1,%2,%3}, [%4];"
                 : "=r"(r[0]), "=r"(r[1]), "=r"(r[2]), "=r"(r[3]) : "r"(addr));
}
__device__ __forceinline__ void mma_hf(float* d, const uint32_t* a, const uint32_t* b) {
    asm volatile("mma.sync.aligned.m16n8k16.row.col.f32.f16.f16.f32 "
                 "{%0,%1,%2,%3}, {%4,%5,%6,%7}, {%8,%9}, {%0,%1,%2,%3};"
                 : "+f"(d[0]), "+f"(d[1]), "+f"(d[2]), "+f"(d[3])
                 : "r"(a[0]), "r"(a[1]), "r"(a[2]), "r"(a[3]), "r"(b[0]), "r"(b[1]));
}

// ---------------- weight convert kernel (fp32 -> fp16) ----------------------------
__global__ void conv_kernel(const float4* __restrict__ in, uint2* __restrict__ out, int n4)
{
    for (int i = blockIdx.x * 256 + threadIdx.x; i < n4; i += gridDim.x * 256) {
        out[i] = cvt4h(in[i]);
    }
}

// ---------------- fp16 GEMM: C = A @ W^T + bias -----------------------------------
// A fp16 [M,K], W fp16 [N,K]. BM=128,BN=128,BK=64. 256 thr, 8 warps (4x2).
// 3-stage cp.async pipeline, 2 CTAs/SM. m0 = ((bid & ((1<<mshift)-1)) + moff)*128.
#define ROWB  144
#define TILEB (128*ROWB)     // 18432
#define BUFB  (2*TILEB)      // 36864
#define NSTG  3
#define GSMEM (NSTG*BUFB)    // 110592

template<bool RELU, bool SPLITOUT, bool MIXOUT>
__global__ void __launch_bounds__(256, 2)
gemm_hs(const __half* __restrict__ A, const __half* __restrict__ W,
        const float* __restrict__ bias, float* __restrict__ C,
        __half* __restrict__ Ch,
        const float* __restrict__ Xin,
        int N, int K, int use_cnt, int mshift, int moff)
{
    int bid = blockIdx.x;
    int m0 = ((bid & ((1 << mshift) - 1)) + moff) << 7;
    int n0 = (bid >> mshift) << 7;
    if (use_cnt) {
        int b = m0 >> 11;
        if ((m0 & 2047) >= g_tcnt[b]) return;
    }

    extern __shared__ char smraw[];
    uint32_t sb = smem_u32(smraw);
    int tid = threadIdx.x, lane = tid & 31, wid = tid >> 5;
    int mw = (wid & 3) << 5;
    int nw = (wid >> 2) << 6;

    int lr = tid >> 3, seg = tid & 7;
    const __half* srcA[4];
    const __half* srcW[4];
    uint32_t dstA[4], dstW[4];
    #pragma unroll
    for (int j = 0; j < 4; ++j) {
        int row = lr + 32 * j;
        srcA[j] = A + (size_t)(m0 + row) * K + seg * 8;
        srcW[j] = W + (size_t)(n0 + row) * K + seg * 8;
        dstA[j] = (uint32_t)(row * ROWB + seg * 16);
        dstW[j] = (uint32_t)(TILEB + row * ROWB + seg * 16);
    }

    int am = lane >> 3;
    int arow = ((am & 1) << 3) | (lane & 7);
    int akc = am >> 1;
    uint32_t offA[2][4];
    #pragma unroll
    for (int mt = 0; mt < 2; ++mt)
        #pragma unroll
        for (int ks = 0; ks < 4; ++ks)
            offA[mt][ks] = (uint32_t)((mw + mt*16 + arow) * ROWB + (ks*2 + akc) * 16);
    int brow = ((am >> 1) << 3) | (lane & 7);
    int bkc = am & 1;
    uint32_t offB[4][4];
    #pragma unroll
    for (int jp = 0; jp < 4; ++jp)
        #pragma unroll
        for (int ks = 0; ks < 4; ++ks)
            offB[jp][ks] = (uint32_t)((nw + jp*16 + brow) * ROWB + (ks*2 + bkc) * 16);

    float acc[2][8][4];
    #pragma unroll
    for (int mt = 0; mt < 2; ++mt)
        #pragma unroll
        for (int nt = 0; nt < 8; ++nt)
            #pragma unroll
            for (int i = 0; i < 4; ++i) acc[mt][nt][i] = 0.f;

    int NC = K >> 6;

    #pragma unroll
    for (int s = 0; s < 2; ++s) {
        uint32_t nb = sb + (uint32_t)s * BUFB;
        const int ko = s * 64;
        #pragma unroll
        for (int j = 0; j < 4; ++j) {
            cpa16(nb + dstA[j], srcA[j] + ko);
            cpa16(nb + dstW[j], srcW[j] + ko);
        }
        cp_commit();
    }

    int slot = 0, pslot = 2;
    for (int c = 0; c < NC; ++c) {
        cp_wait<1>();
        __syncthreads();

        if (c + 2 < NC) {
            uint32_t nb = sb + (uint32_t)pslot * BUFB;
            const int ko = (c + 2) * 64;
            #pragma unroll
            for (int j = 0; j < 4; ++j) {
                cpa16(nb + dstA[j], srcA[j] + ko);
                cpa16(nb + dstW[j], srcW[j] + ko);
            }
        }
        cp_commit();

        uint32_t cb = sb + (uint32_t)slot * BUFB;
        #pragma unroll
        for (int ks = 0; ks < 4; ++ks) {
            uint32_t ah[2][4], w[4][4];
            ldm4(cb + offA[0][ks], ah[0]);
            ldm4(cb + offA[1][ks], ah[1]);
            #pragma unroll
            for (int jp = 0; jp < 4; ++jp)
                ldm4(cb + TILEB + offB[jp][ks], w[jp]);
            #pragma unroll
            for (int mt = 0; mt < 2; ++mt)
                #pragma unroll
                for (int nt = 0; nt < 8; ++nt) {
                    const uint32_t* bw = &w[nt >> 1][(nt & 1) * 2];
                    mma_hf(acc[mt][nt], ah[mt], bw);
                }
        }
        slot  = (slot  == NSTG-1) ? 0 : slot  + 1;
        pslot = (pslot == NSTG-1) ? 0 : pslot + 1;
    }

    #pragma unroll
    for (int mt = 0; mt < 2; ++mt)
        #pragma unroll
        for (int nt = 0; nt < 8; ++nt) {
            float* a = acc[mt][nt];
            int col = n0 + nw + nt * 8 + (lane & 3) * 2;
            int r0  = m0 + mw + mt * 16 + (lane >> 2);
            float2 bv = *(const float2*)(bias + col);
            float x0 = a[0] + bv.x, y0 = a[1] + bv.y;
            float x1 = a[2] + bv.x, y1 = a[3] + bv.y;
            if (RELU) {
                x0 = fmaxf(x0, 0.f); y0 = fmaxf(y0, 0.f);
                x1 = fmaxf(x1, 0.f); y1 = fmaxf(y1, 0.f);
            }
            if (MIXOUT) {
                float e0 = g_eff[r0], e1 = g_eff[r0 + 8];
                float2 xa = *(const float2*)(Xin + (size_t)r0 * N + col);
                float2 xb = *(const float2*)(Xin + (size_t)(r0 + 8) * N + col);
                x0 = (1.f - e0) * xa.x + e0 * x0;
                y0 = (1.f - e0) * xa.y + e0 * y0;
                x1 = (1.f - e1) * xb.x + e1 * x1;
                y1 = (1.f - e1) * xb.y + e1 * y1;
                *(uint32_t*)(Ch + (size_t)r0 * N + col) =
                    pk2h(__float2half_rn(x0), __float2half_rn(y0));
                *(uint32_t*)(Ch + (size_t)(r0 + 8) * N + col) =
                    pk2h(__float2half_rn(x1), __float2half_rn(y1));
            } else if (SPLITOUT) {
                *(uint32_t*)(Ch + (size_t)r0 * N + col) =
                    pk2h(__float2half_rn(x0), __float2half_rn(y0));
                *(uint32_t*)(Ch + (size_t)(r0 + 8) * N + col) =
                    pk2h(__float2half_rn(x1), __float2half_rn(y1));
            } else {
                float2 v0 = {x0, y0}, v1 = {x1, y1};
                *(float2*)(C + (size_t)r0 * N + col) = v0;
                *(float2*)(C + (size_t)(r0 + 8) * N + col) = v1;
            }
        }
}

// ---------------- mask + compaction (1 warp per batch) ---------------------------
__global__ void mask_kernel(const int* __restrict__ ids,
                            const int* __restrict__ sotp,
                            const int* __restrict__ eotp)
{
    int b = blockIdx.x;
    int lane = threadIdx.x;
    int sot = *sotp, eot = *eotp;
    const int* row = ids + b * Sn;
    int base = lane * 64;

    unsigned a = 0u, bb = 1u, anyeot = 0u;
    for (int i = 0; i < 64; ++i) {
        int t = row[base + i];
        unsigned iso = (t == sot) ? 1u : 0u;
        unsigned ieo = (t == eot) ? 1u : 0u;
        a = iso | (a & (1u - ieo));
        bb = bb & (1u - ieo);
        anyeot |= ieo;
    }
    unsigned ai = a, bi = bb;
    for (int off = 1; off < 32; off <<= 1) {
        unsigned ap = __shfl_up_sync(0xffffffffu, ai, off);
        unsigned bp = __shfl_up_sync(0xffffffffu, bi, off);
        if (lane >= off) { ai = ai | (ap & bi); bi = bi & bp; }
    }
    unsigned s_in = __shfl_up_sync(0xffffffffu, ai, 1);
    if (lane == 0) s_in = 0u;

    unsigned sfx = anyeot;
    for (int off = 1; off < 32; off <<= 1) {
        unsigned v = __shfl_down_sync(0xffffffffu, sfx, off);
        if (lane + off < 32) sfx |= v;
    }
    unsigned after = __shfl_down_sync(0xffffffffu, sfx, 1);
    if (lane == 31) after = 0u;

    unsigned long long openbits = 0ull;
    unsigned s = s_in;
    for (int i = 0; i < 64; ++i) {
        int t = row[base + i];
        unsigned iso = (t == sot) ? 1u : 0u;
        unsigned ieo = (t == eot) ? 1u : 0u;
        unsigned o = iso | s;
        openbits |= ((unsigned long long)o) << i;
        s = iso | (s & (1u - ieo));
    }
    unsigned long long tbits = 0ull;
    unsigned seen = after;
    for (int i = 63; i >= 0; --i) {
        int t = row[base + i];
        if (t == eot) seen = 1u;
        if (((openbits >> i) & 1ull) && seen) tbits |= (1ull << i);
    }
    int c = __popcll(tbits);
    int pre = c;
    for (int off = 1; off < 32; off <<= 1) {
        int v = __shfl_up_sync(0xffffffffu, pre, off);
        if (lane >= off) pre += v;
    }
    int excl = pre - c;
    int total = __shfl_sync(0xffffffffu, pre, 31);
    if (lane == 31) g_tcnt[b] = total;
    int o = excl;
    for (int i = 0; i < 64; ++i) {
        if ((tbits >> i) & 1ull) g_tidx[b * Sn + (o++)] = base + i;
    }
}

// ---------------- gather thought rows: fp32 + fp16 --------------------------------
__global__ void gather_kernel(const float* __restrict__ x)
{
    int b = blockIdx.y, i = blockIdx.x;
    if (i >= g_tcnt[b]) return;
    int src = b * Sn + g_tidx[b * Sn + i];
    int t = threadIdx.x;
    float4 v = ((const float4*)(x + (size_t)src * Dn))[t];
    size_t rb = (size_t)(b * Sn + i) * Dn;
    ((float4*)(g_Xc + rb))[t] = v;
    ((uint2*)(g_Xc_h + rb))[t] = cvt4h(v);
}

// ---------------- attention over compacted thought rows (per batch) ---------------
__global__ void __launch_bounds__(256) attn_kernel(int b)
{
    int h = blockIdx.y, qt = blockIdx.x;
    int nT = g_tcnt[b];
    if (qt * 32 >= nT) return;

    __shared__ float Ks[128][33];
    __shared__ float Vs[32][128];
    __shared__ float Qs[32][132];

    int tid = threadIdx.x, warp = tid >> 5, lane = tid & 31;
    int qb[4]; bool qv[4];
    #pragma unroll
    for (int qq = 0; qq < 4; ++qq) {
        qb[qq] = qt * 32 + warp + 8 * qq;
        qv[qq] = qb[qq] < nT;
        if (qv[qq]) {
            const float* qr = g_qkv + (size_t)(b*Sn + qb[qq]) * (3*Dn) + h * DHn;
            #pragma unroll
            for (int c = 0; c < 4; ++c) Qs[warp + 8*qq][lane + 32*c] = qr[lane + 32*c];
        }
    }

    float mx[4], ls[4], acc[4][4];
    #pragma unroll
    for (int qq = 0; qq < 4; ++qq) {
        mx[qq] = -1e30f; ls[qq] = 0.f;
        #pragma unroll
        for (int c = 0; c < 4; ++c) acc[qq][c] = 0.f;
    }
    const float scale = 0.088388347648318447f;

    for (int j0 = 0; j0 < nT; j0 += 32) {
        int jn = min(32, nT - j0);
        __syncthreads();
        for (int idx = tid; idx < 32*128; idx += 256) {
            int j = idx >> 7, d = idx & 127;
            float kv = 0.f, vv = 0.f;
            if (j < jn) {
                const float* kr = g_qkv + (size_t)(b*Sn + j0 + j)*(3*Dn) + Dn + h*DHn;
                kv = kr[d];
                vv = kr[Dn + d];
            }
            Ks[d][j] = kv;
            Vs[j][d] = vv;
        }
        __syncthreads();

        float s[4] = {0.f, 0.f, 0.f, 0.f};
#pragma unroll 4
        for (int d = 0; d < 128; ++d) {
            float kv = Ks[d][lane];
            #pragma unroll
            for (int qq = 0; qq < 4; ++qq) s[qq] += Qs[warp + 8*qq][d] * kv;
        }
        float p[4], cr[4];
        #pragma unroll
        for (int qq = 0; qq < 4; ++qq) {
            float sq = s[qq] * scale;
            if (lane >= jn) sq = -1e30f;
            float sm = sq;
            #pragma unroll
            for (int off = 16; off; off >>= 1)
                sm = fmaxf(sm, __shfl_xor_sync(0xffffffffu, sm, off));
            float mn = fmaxf(mx[qq], sm);
            p[qq] = (lane < jn) ? __expf(sq - mn) : 0.f;
            float ps = p[qq];
            #pragma unroll
            for (int off = 16; off; off >>= 1)
                ps += __shfl_xor_sync(0xffffffffu, ps, off);
            cr[qq] = __expf(mx[qq] - mn);
            ls[qq] = ls[qq] * cr[qq] + ps;
            mx[qq] = mn;
        }
        #pragma unroll
        for (int qq = 0; qq < 4; ++qq)
            #pragma unroll
            for (int c = 0; c < 4; ++c) acc[qq][c] *= cr[qq];
        for (int j = 0; j < jn; ++j) {
            float pj[4];
            #pragma unroll
            for (int qq = 0; qq < 4; ++qq)
                pj[qq] = __shfl_sync(0xffffffffu, p[qq], j);
            #pragma unroll
            for (int c = 0; c < 4; ++c) {
                float vv = Vs[j][lane + 32*c];
                #pragma unroll
                for (int qq = 0; qq < 4; ++qq) acc[qq][c] += pj[qq] * vv;
            }
        }
    }
    #pragma unroll
    for (int qq = 0; qq < 4; ++qq) {
        if (qv[qq]) {
            float inv = 1.f / ls[qq];
            size_t rb = (size_t)(b*Sn + qb[qq]) * Dn + h * DHn;
            #pragma unroll
            for (int c = 0; c < 4; ++c)
                g_ctx_h[rb + lane + 32*c] = __float2half_rn(acc[qq][c] * inv);
        }
    }
}

// ---------------- block reduction helper ------------------------------------------
__device__ __forceinline__ float block_sum256(float v, float* red)
{
    int lane = threadIdx.x & 31, warp = threadIdx.x >> 5;
#pragma unroll
    for (int off = 16; off; off >>= 1) v += __shfl_xor_sync(0xffffffffu, v, off);
    if (lane == 0) red[warp] = v;
    __syncthreads();
    if (warp == 0) {
        float t = (lane < 8) ? red[lane] : 0.f;
#pragma unroll
        for (int off = 4; off; off >>= 1) t += __shfl_xor_sync(0xffffffffu, t, off);
        if (lane == 0) red[0] = t;
    }
    __syncthreads();
    float r = red[0];
    __syncthreads();
    return r;
}

// ---------------- fused residual-add + LayerNorm (per-batch via roff) -------------
__global__ void __launch_bounds__(256) add_ln_kernel(
    const float* __restrict__ X, const float* __restrict__ Y,
    const float* __restrict__ g, const float* __restrict__ be,
    float* __restrict__ out, __half* __restrict__ oh, int use_cnt, int roff)
{
    int r = blockIdx.x + roff;
    if (use_cnt) { int b = r >> 11; if ((r & 2047) >= g_tcnt[b]) return; }
    __shared__ float red[8];
    int t = threadIdx.x;
    float4 xv = ((const float4*)(X + (size_t)r * Dn))[t];
    float4 yv = ((const float4*)(Y + (size_t)r * Dn))[t];
    float v0 = xv.x + yv.x, v1 = xv.y + yv.y, v2 = xv.z + yv.z, v3 = xv.w + yv.w;
    float mu = block_sum256(v0 + v1 + v2 + v3, red) * (1.0f / Dn);
    float d0 = v0 - mu, d1 = v1 - mu, d2 = v2 - mu, d3 = v3 - mu;
    float var = block_sum256(d0*d0 + d1*d1 + d2*d2 + d3*d3, red) * (1.0f / Dn);
    float inv = rsqrtf(var + 1e-5f);
    float4 gv = ((const float4*)g)[t];
    float4 bv = ((const float4*)be)[t];
    float4 o;
    o.x = d0 * inv * gv.x + bv.x;
    o.y = d1 * inv * gv.y + bv.y;
    o.z = d2 * inv * gv.z + bv.z;
    o.w = d3 * inv * gv.w + bv.w;
    ((float4*)(out + (size_t)r * Dn))[t] = o;
    if (oh) ((uint2*)(oh + (size_t)r * Dn))[t] = cvt4h(o);
}

// ---------------- cat init: cat = [x | x] (fp16), eff = 0.1 ------------------------
__global__ void init_cat_kernel(const float* __restrict__ x)
{
    int r = blockIdx.x, t = threadIdx.x;
    float4 v = ((const float4*)(x + (size_t)r * Dn))[t];
    uint2 h = cvt4h(v);
    uint2* ch = (uint2*)(g_cat_h + (size_t)r * 2 * Dn);
    ch[t] = h; ch[t + 256] = h;
    if (t == 0) g_eff[r] = 0.1f;
}

// ---------------- scatter x2 into cat[:, D:] (fp16) + gate (per batch) ------------
__global__ void __launch_bounds__(256) scatter_kernel(
    const float* __restrict__ Wg, const float* __restrict__ bg, int b)
{
    int i = blockIdx.x;
    if (i >= g_tcnt[b]) return;
    __shared__ float red[8];
    int dst = b * Sn + g_tidx[b * Sn + i];
    int t = threadIdx.x;
    float4 v = ((const float4*)(g_x2 + (size_t)(b*Sn + i) * Dn))[t];
    ((uint2*)(g_cat_h + (size_t)dst * 2 * Dn + Dn))[t] = cvt4h(v);
    float4 w = ((const float4*)Wg)[t];
    float p = v.x*w.x + v.y*w.y + v.z*w.z + v.w*w.w;
    float tot = block_sum256(p, red);
    if (t == 0) g_eff[dst] = 1.f / (1.f + __expf(-(tot + bg[0])));
}

// ---------------- launch ------------------------------------------------------------
#define SYM(p, s) cudaGetSymbolAddress((void**)&p, s)

extern "C" void kernel_launch(void* const* d_in, const int* in_sizes, int n_in,
                              void* d_out, int out_size)
{
    const float* x    = (const float*)d_in[0];
    const int*   ids  = (const int*)d_in[1];
    const int*   sot  = (const int*)d_in[2];
    const int*   eot  = (const int*)d_in[3];
    const float* Wqkv = (const float*)d_in[4];
    const float* bqkv = (const float*)d_in[5];
    const float* Wo   = (const float*)d_in[6];
    const float* bo   = (const float*)d_in[7];
    const float* ln1g = (const float*)d_in[8];
    const float* ln1b = (const float*)d_in[9];
    const float* W1   = (const float*)d_in[10];
    const float* b1   = (const float*)d_in[11];
    const float* W2   = (const float*)d_in[12];
    const float* b2   = (const float*)d_in[13];
    const float* ln2g = (const float*)d_in[14];
    const float* ln2b = (const float*)d_in[15];
    const float* Wg   = (const float*)d_in[16];
    const float* bg   = (const float*)d_in[17];
    const float* Wm   = (const float*)d_in[18];
    const float* bm   = (const float*)d_in[19];
    const float* Wout = (const float*)d_in[20];
    const float* bout = (const float*)d_in[21];
    float* out = (float*)d_out;

    float *pXc, *pqkv, *pattno, *px1, *pff, *px2;
    __half *pXch, *pctxh, *px1h, *phffh, *pcath, *pmixh;
    __half *pWqkvh, *pWoh, *pW1h, *pW2h, *pWmh, *pWouth;
    SYM(pXc, g_Xc); SYM(pqkv, g_qkv); SYM(pattno, g_attno); SYM(px1, g_x1);
    SYM(pff, g_ff); SYM(px2, g_x2);
    SYM(pXch, g_Xc_h); SYM(pctxh, g_ctx_h); SYM(px1h, g_x1_h); SYM(phffh, g_hff_h);
    SYM(pcath, g_cat_h); SYM(pmixh, g_mix_h);
    SYM(pWqkvh, g_Wqkv_h); SYM(pWoh, g_Wo_h); SYM(pW1h, g_W1_h); SYM(pW2h, g_W2_h);
    SYM(pWmh, g_Wm_h); SYM(pWouth, g_Wout_h);

    cudaFuncSetAttribute(gemm_hs<false,false,false>, cudaFuncAttributeMaxDynamicSharedMemorySize, GSMEM);
    cudaFuncSetAttribute(gemm_hs<true,true,false>,   cudaFuncAttributeMaxDynamicSharedMemorySize, GSMEM);
    cudaFuncSetAttribute(gemm_hs<false,false,true>,  cudaFuncAttributeMaxDynamicSharedMemorySize, GSMEM);

    // one-time stream/event setup (host-side objects; no device allocations)
    static cudaStream_t s1 = nullptr;
    static cudaEvent_t evF = nullptr, evW = nullptr, evR = nullptr, evG = nullptr, evD = nullptr;
    if (!s1) {
        cudaStreamCreateWithFlags(&s1, cudaStreamNonBlocking);
        cudaEventCreateWithFlags(&evF, cudaEventDisableTiming);
        cudaEventCreateWithFlags(&evW, cudaEventDisableTiming);
        cudaEventCreateWithFlags(&evR, cudaEventDisableTiming);
        cudaEventCreateWithFlags(&evG, cudaEventDisableTiming);
        cudaEventCreateWithFlags(&evD, cudaEventDisableTiming);
    }

    // tail of the per-batch chain: everything from Wo onward (needs all weights)
    auto chain_tail = [&](cudaStream_t st, int b) {
        int mo = 16 * b;
        gemm_hs<false,false,false><<<16*8, 256, GSMEM, st>>>(pctxh, pWoh, bo, pattno, nullptr, nullptr, Dn, Dn, 1, 4, mo);
        add_ln_kernel<<<Sn, 256, 0, st>>>(pXc, pattno, ln1g, ln1b, px1, px1h, 1, b*Sn);
        gemm_hs<true,true,false><<<16*32, 256, GSMEM, st>>>(px1h, pW1h, b1, nullptr, phffh, nullptr, DFFn, Dn, 1, 4, mo);
        gemm_hs<false,false,false><<<16*8, 256, GSMEM, st>>>(phffh, pW2h, b2, pff, nullptr, nullptr, Dn, DFFn, 1, 4, mo);
        add_ln_kernel<<<Sn, 256, 0, st>>>(px1, pff, ln2g, ln2b, px2, nullptr, 1, b*Sn);
        scatter_kernel<<<Sn, 256, 0, st>>>(Wg, bg, b);
        gemm_hs<false,false,true><<<16*8, 256, GSMEM, st>>>(pcath, pWmh, bm, nullptr, pmixh, x, Dn, 2*Dn, 0, 4, mo);
        gemm_hs<false,false,false><<<16*250, 256, GSMEM, st>>>(pmixh, pWouth, bout, out, nullptr, nullptr, Vn, Dn, 0, 4, mo);
    };

    // ---- fork: convs + init_cat on s1 ----
    cudaEventRecord(evF, 0);
    cudaStreamWaitEvent(s1, evF, 0);
    conv_kernel<<<512, 256, 0, s1>>>((const float4*)Wqkv, (uint2*)pWqkvh, 3*Dn*Dn/4);
    cudaEventRecord(evW, s1);   // Wqkv ready — batch-0 QKV can start
    conv_kernel<<<256, 256, 0, s1>>>((const float4*)Wo,   (uint2*)pWoh,   Dn*Dn/4);
    conv_kernel<<<512, 256, 0, s1>>>((const float4*)W1,   (uint2*)pW1h,   DFFn*Dn/4);
    conv_kernel<<<512, 256, 0, s1>>>((const float4*)W2,   (uint2*)pW2h,   Dn*DFFn/4);
    conv_kernel<<<512, 256, 0, s1>>>((const float4*)Wm,   (uint2*)pWmh,   Dn*2*Dn/4);
    conv_kernel<<<2048, 256, 0, s1>>>((const float4*)Wout,(uint2*)pWouth, Vn*Dn/4);
    init_cat_kernel<<<Rn, 256, 0, s1>>>(x);
    cudaEventRecord(evR, s1);   // all weights + init_cat ready

    // ---- stream 0: mask + gather ----
    mask_kernel<<<Bn, 32>>>(ids, sot, eot);
    gather_kernel<<<dim3(Sn, Bn), 256>>>(x);
    cudaEventRecord(evG, 0);

    // ---- s1: batch-1 chain (its convs precede in-stream; only gather is cross) ----
    cudaStreamWaitEvent(s1, evG, 0);
    gemm_hs<false,false,false><<<16*24, 256, GSMEM, s1>>>(pXch, pWqkvh, bqkv, pqkv, nullptr, nullptr, 3*Dn, Dn, 1, 4, 16);
    attn_kernel<<<dim3(Sn/32, NHEADS), 256, 0, s1>>>(1);
    chain_tail(s1, 1);
    cudaEventRecord(evD, s1);

    // ---- stream 0: batch-0 chain; QKV+attn overlap remaining convs ----
    cudaStreamWaitEvent(0, evW, 0);   // only Wqkv needed for QKV
    gemm_hs<false,false,false><<<16*24, 256, GSMEM>>>(pXch, pWqkvh, bqkv, pqkv, nullptr, nullptr, 3*Dn, Dn, 1, 4, 0);
    attn_kernel<<<dim3(Sn/32, NHEADS), 256>>>(0);
    cudaStreamWaitEvent(0, evR, 0);   // join remaining convs + init_cat before Wo/W1/...
    chain_tail(0, 0);
    cudaStreamWaitEvent(0, evD, 0);   // join batch-1 chain

    (void)in_sizes; (void)n_in; (void)out_size;
}

// round 13
// speedup vs baseline: 1.0324x; 1.0324x over previous
#include <cuda_runtime.h>
#include <cuda_fp16.h>
#include <cstdint>

// ---------------- problem constants ----------------
#define Bn 2
#define Sn 2048
#define Dn 1024
#define Vn 32000
#define NHEADS 8
#define DHn 128
#define DFFn 4096
#define Rn (Bn*Sn)   // 4096 total rows

// ---------------- fp32 scratch ----------------
__device__ float g_Xc[Rn*Dn];
__device__ float g_qkv[Rn*3*Dn];
__device__ float g_attno[Rn*Dn];
__device__ float g_x1[Rn*Dn];
__device__ float g_ff[Rn*Dn];
__device__ float g_x2[Rn*Dn];
__device__ float g_eff[Rn];
__device__ int   g_tidx[Rn];
__device__ int   g_tcnt[Bn];

// ---------------- fp16 planes ---------------------------------
__device__ __align__(16) __half g_Xc_h[Rn*Dn];
__device__ __align__(16) __half g_ctx_h[Rn*Dn];
__device__ __align__(16) __half g_x1_h[Rn*Dn];
__device__ __align__(16) __half g_hff_h[Rn*DFFn];
__device__ __align__(16) __half g_cat_h[Rn*2*Dn];
__device__ __align__(16) __half g_mix_h[Rn*Dn];
__device__ __align__(16) __half g_Wqkv_h[3*Dn*Dn];
__device__ __align__(16) __half g_Wo_h[Dn*Dn];
__device__ __align__(16) __half g_W1_h[DFFn*Dn];
__device__ __align__(16) __half g_W2_h[Dn*DFFn];
__device__ __align__(16) __half g_Wm_h[Dn*2*Dn];
__device__ __align__(16) __half g_Wout_h[Vn*Dn];

// ---------------- helpers -------------------------------------------------------
__device__ __forceinline__ uint32_t smem_u32(const void* p) {
    uint32_t a;
    asm("{ .reg .u64 t; cvta.to.shared.u64 t, %1; cvt.u32.u64 %0, t; }" : "=r"(a) : "l"(p));
    return a;
}
__device__ __forceinline__ uint32_t pk2h(__half a, __half b) {
    return ((uint32_t)__half_as_ushort(b) << 16) | (uint32_t)__half_as_ushort(a);
}
__device__ __forceinline__ uint2 cvt4h(float4 v) {
    uint2 h;
    h.x = pk2h(__float2half_rn(v.x), __float2half_rn(v.y));
    h.y = pk2h(__float2half_rn(v.z), __float2half_rn(v.w));
    return h;
}
__device__ __forceinline__ void cpa16(uint32_t dst, const void* src) {
    asm volatile("cp.async.cg.shared.global [%0], [%1], 16;" :: "r"(dst), "l"(src));
}
__device__ __forceinline__ void cp_commit() {
    asm volatile("cp.async.commit_group;" ::: "memory");
}
template<int N>
__device__ __forceinline__ void cp_wait() {
    asm volatile("cp.async.wait_group %0;" :: "n"(N) : "memory");
}
__device__ __forceinline__ void ldm4(uint32_t addr, uint32_t* r) {
    asm volatile("ldmatrix.sync.aligned.m8n8.x4.shared.b16 {%0,%1,%2,%3}, [%4];"
                 : "=r"(r[0]), "=r"(r[1]), "=r"(r[2]), "=r"(r[3]) : "r"(addr));
}
__device__ __forceinline__ void mma_hf(float* d, const uint32_t* a, const uint32_t* b) {
    asm volatile("mma.sync.aligned.m16n8k16.row.col.f32.f16.f16.f32 "
                 "{%0,%1,%2,%3}, {%4,%5,%6,%7}, {%8,%9}, {%0,%1,%2,%3};"
                 : "+f"(d[0]), "+f"(d[1]), "+f"(d[2]), "+f"(d[3])
                 : "r"(a[0]), "r"(a[1]), "r"(a[2]), "r"(a[3]), "r"(b[0]), "r"(b[1]));
}

// ---------------- weight convert kernel (fp32 -> fp16) ----------------------------
__global__ void conv_kernel(const float4* __restrict__ in, uint2* __restrict__ out, int n4)
{
    for (int i = blockIdx.x * 256 + threadIdx.x; i < n4; i += gridDim.x * 256) {
        out[i] = cvt4h(in[i]);
    }
}

// ---------------- fp16 GEMM: C = A @ W^T + bias -----------------------------------
// A fp16 [M,K], W fp16 [N,K]. BM=128,BN=128,BK=64. 256 thr, 8 warps (4x2).
// 3-stage cp.async pipeline, 2 CTAs/SM. m0 = ((bid & ((1<<mshift)-1)) + moff)*128.
#define ROWB  144
#define TILEB (128*ROWB)     // 18432
#define BUFB  (2*TILEB)      // 36864
#define NSTG  3
#define GSMEM (NSTG*BUFB)    // 110592

template<bool RELU, bool SPLITOUT, bool MIXOUT>
__global__ void __launch_bounds__(256, 2)
gemm_hs(const __half* __restrict__ A, const __half* __restrict__ W,
        const float* __restrict__ bias, float* __restrict__ C,
        __half* __restrict__ Ch,
        const float* __restrict__ Xin,
        int N, int K, int use_cnt, int mshift, int moff)
{
    int bid = blockIdx.x;
    int m0 = ((bid & ((1 << mshift) - 1)) + moff) << 7;
    int n0 = (bid >> mshift) << 7;
    if (use_cnt) {
        int b = m0 >> 11;
        if ((m0 & 2047) >= g_tcnt[b]) return;
    }

    extern __shared__ char smraw[];
    uint32_t sb = smem_u32(smraw);
    int tid = threadIdx.x, lane = tid & 31, wid = tid >> 5;
    int mw = (wid & 3) << 5;
    int nw = (wid >> 2) << 6;

    int lr = tid >> 3, seg = tid & 7;
    const __half* srcA[4];
    const __half* srcW[4];
    uint32_t dstA[4], dstW[4];
    #pragma unroll
    for (int j = 0; j < 4; ++j) {
        int row = lr + 32 * j;
        srcA[j] = A + (size_t)(m0 + row) * K + seg * 8;
        srcW[j] = W + (size_t)(n0 + row) * K + seg * 8;
        dstA[j] = (uint32_t)(row * ROWB + seg * 16);
        dstW[j] = (uint32_t)(TILEB + row * ROWB + seg * 16);
    }

    int am = lane >> 3;
    int arow = ((am & 1) << 3) | (lane & 7);
    int akc = am >> 1;
    uint32_t offA[2][4];
    #pragma unroll
    for (int mt = 0; mt < 2; ++mt)
        #pragma unroll
        for (int ks = 0; ks < 4; ++ks)
            offA[mt][ks] = (uint32_t)((mw + mt*16 + arow) * ROWB + (ks*2 + akc) * 16);
    int brow = ((am >> 1) << 3) | (lane & 7);
    int bkc = am & 1;
    uint32_t offB[4][4];
    #pragma unroll
    for (int jp = 0; jp < 4; ++jp)
        #pragma unroll
        for (int ks = 0; ks < 4; ++ks)
            offB[jp][ks] = (uint32_t)((nw + jp*16 + brow) * ROWB + (ks*2 + bkc) * 16);

    float acc[2][8][4];
    #pragma unroll
    for (int mt = 0; mt < 2; ++mt)
        #pragma unroll
        for (int nt = 0; nt < 8; ++nt)
            #pragma unroll
            for (int i = 0; i < 4; ++i) acc[mt][nt][i] = 0.f;

    int NC = K >> 6;

    #pragma unroll
    for (int s = 0; s < 2; ++s) {
        uint32_t nb = sb + (uint32_t)s * BUFB;
        const int ko = s * 64;
        #pragma unroll
        for (int j = 0; j < 4; ++j) {
            cpa16(nb + dstA[j], srcA[j] + ko);
            cpa16(nb + dstW[j], srcW[j] + ko);
        }
        cp_commit();
    }

    int slot = 0, pslot = 2;
    for (int c = 0; c < NC; ++c) {
        cp_wait<1>();
        __syncthreads();

        if (c + 2 < NC) {
            uint32_t nb = sb + (uint32_t)pslot * BUFB;
            const int ko = (c + 2) * 64;
            #pragma unroll
            for (int j = 0; j < 4; ++j) {
                cpa16(nb + dstA[j], srcA[j] + ko);
                cpa16(nb + dstW[j], srcW[j] + ko);
            }
        }
        cp_commit();

        uint32_t cb = sb + (uint32_t)slot * BUFB;
        #pragma unroll
        for (int ks = 0; ks < 4; ++ks) {
            uint32_t ah[2][4], w[4][4];
            ldm4(cb + offA[0][ks], ah[0]);
            ldm4(cb + offA[1][ks], ah[1]);
            #pragma unroll
            for (int jp = 0; jp < 4; ++jp)
                ldm4(cb + TILEB + offB[jp][ks], w[jp]);
            #pragma unroll
            for (int mt = 0; mt < 2; ++mt)
                #pragma unroll
                for (int nt = 0; nt < 8; ++nt) {
                    const uint32_t* bw = &w[nt >> 1][(nt & 1) * 2];
                    mma_hf(acc[mt][nt], ah[mt], bw);
                }
        }
        slot  = (slot  == NSTG-1) ? 0 : slot  + 1;
        pslot = (pslot == NSTG-1) ? 0 : pslot + 1;
    }

    #pragma unroll
    for (int mt = 0; mt < 2; ++mt)
        #pragma unroll
        for (int nt = 0; nt < 8; ++nt) {
            float* a = acc[mt][nt];
            int col = n0 + nw + nt * 8 + (lane & 3) * 2;
            int r0  = m0 + mw + mt * 16 + (lane >> 2);
            float2 bv = *(const float2*)(bias + col);
            float x0 = a[0] + bv.x, y0 = a[1] + bv.y;
            float x1 = a[2] + bv.x, y1 = a[3] + bv.y;
            if (RELU) {
                x0 = fmaxf(x0, 0.f); y0 = fmaxf(y0, 0.f);
                x1 = fmaxf(x1, 0.f); y1 = fmaxf(y1, 0.f);
            }
            if (MIXOUT) {
                float e0 = g_eff[r0], e1 = g_eff[r0 + 8];
                float2 xa = *(const float2*)(Xin + (size_t)r0 * N + col);
                float2 xb = *(const float2*)(Xin + (size_t)(r0 + 8) * N + col);
                x0 = (1.f - e0) * xa.x + e0 * x0;
                y0 = (1.f - e0) * xa.y + e0 * y0;
                x1 = (1.f - e1) * xb.x + e1 * x1;
                y1 = (1.f - e1) * xb.y + e1 * y1;
                *(uint32_t*)(Ch + (size_t)r0 * N + col) =
                    pk2h(__float2half_rn(x0), __float2half_rn(y0));
                *(uint32_t*)(Ch + (size_t)(r0 + 8) * N + col) =
                    pk2h(__float2half_rn(x1), __float2half_rn(y1));
            } else if (SPLITOUT) {
                *(uint32_t*)(Ch + (size_t)r0 * N + col) =
                    pk2h(__float2half_rn(x0), __float2half_rn(y0));
                *(uint32_t*)(Ch + (size_t)(r0 + 8) * N + col) =
                    pk2h(__float2half_rn(x1), __float2half_rn(y1));
            } else {
                float2 v0 = {x0, y0}, v1 = {x1, y1};
                *(float2*)(C + (size_t)r0 * N + col) = v0;
                *(float2*)(C + (size_t)(r0 + 8) * N + col) = v1;
            }
        }
}

// ---------------- mask + compaction (1 warp per batch) ---------------------------
__global__ void mask_kernel(const int* __restrict__ ids,
                            const int* __restrict__ sotp,
                            const int* __restrict__ eotp)
{
    int b = blockIdx.x;
    int lane = threadIdx.x;
    int sot = *sotp, eot = *eotp;
    const int* row = ids + b * Sn;
    int base = lane * 64;

    unsigned a = 0u, bb = 1u, anyeot = 0u;
    for (int i = 0; i < 64; ++i) {
        int t = row[base + i];
        unsigned iso = (t == sot) ? 1u : 0u;
        unsigned ieo = (t == eot) ? 1u : 0u;
        a = iso | (a & (1u - ieo));
        bb = bb & (1u - ieo);
        anyeot |= ieo;
    }
    unsigned ai = a, bi = bb;
    for (int off = 1; off < 32; off <<= 1) {
        unsigned ap = __shfl_up_sync(0xffffffffu, ai, off);
        unsigned bp = __shfl_up_sync(0xffffffffu, bi, off);
        if (lane >= off) { ai = ai | (ap & bi); bi = bi & bp; }
    }
    unsigned s_in = __shfl_up_sync(0xffffffffu, ai, 1);
    if (lane == 0) s_in = 0u;

    unsigned sfx = anyeot;
    for (int off = 1; off < 32; off <<= 1) {
        unsigned v = __shfl_down_sync(0xffffffffu, sfx, off);
        if (lane + off < 32) sfx |= v;
    }
    unsigned after = __shfl_down_sync(0xffffffffu, sfx, 1);
    if (lane == 31) after = 0u;

    unsigned long long openbits = 0ull;
    unsigned s = s_in;
    for (int i = 0; i < 64; ++i) {
        int t = row[base + i];
        unsigned iso = (t == sot) ? 1u : 0u;
        unsigned ieo = (t == eot) ? 1u : 0u;
        unsigned o = iso | s;
        openbits |= ((unsigned long long)o) << i;
        s = iso | (s & (1u - ieo));
    }
    unsigned long long tbits = 0ull;
    unsigned seen = after;
    for (int i = 63; i >= 0; --i) {
        int t = row[base + i];
        if (t == eot) seen = 1u;
        if (((openbits >> i) & 1ull) && seen) tbits |= (1ull << i);
    }
    int c = __popcll(tbits);
    int pre = c;
    for (int off = 1; off < 32; off <<= 1) {
        int v = __shfl_up_sync(0xffffffffu, pre, off);
        if (lane >= off) pre += v;
    }
    int excl = pre - c;
    int total = __shfl_sync(0xffffffffu, pre, 31);
    if (lane == 31) g_tcnt[b] = total;
    int o = excl;
    for (int i = 0; i < 64; ++i) {
        if ((tbits >> i) & 1ull) g_tidx[b * Sn + (o++)] = base + i;
    }
}

// ---------------- gather thought rows: fp32 + fp16 --------------------------------
__global__ void gather_kernel(const float* __restrict__ x)
{
    int b = blockIdx.y, i = blockIdx.x;
    if (i >= g_tcnt[b]) return;
    int src = b * Sn + g_tidx[b * Sn + i];
    int t = threadIdx.x;
    float4 v = ((const float4*)(x + (size_t)src * Dn))[t];
    size_t rb = (size_t)(b * Sn + i) * Dn;
    ((float4*)(g_Xc + rb))[t] = v;
    ((uint2*)(g_Xc_h + rb))[t] = cvt4h(v);
}

// ---------------- attention over compacted thought rows (per batch) ---------------
__global__ void __launch_bounds__(256) attn_kernel(int b)
{
    int h = blockIdx.y, qt = blockIdx.x;
    int nT = g_tcnt[b];
    if (qt * 32 >= nT) return;

    __shared__ float Ks[128][33];
    __shared__ float Vs[32][128];
    __shared__ float Qs[32][132];

    int tid = threadIdx.x, warp = tid >> 5, lane = tid & 31;
    int qb[4]; bool qv[4];
    #pragma unroll
    for (int qq = 0; qq < 4; ++qq) {
        qb[qq] = qt * 32 + warp + 8 * qq;
        qv[qq] = qb[qq] < nT;
        if (qv[qq]) {
            const float* qr = g_qkv + (size_t)(b*Sn + qb[qq]) * (3*Dn) + h * DHn;
            #pragma unroll
            for (int c = 0; c < 4; ++c) Qs[warp + 8*qq][lane + 32*c] = qr[lane + 32*c];
        }
    }

    float mx[4], ls[4], acc[4][4];
    #pragma unroll
    for (int qq = 0; qq < 4; ++qq) {
        mx[qq] = -1e30f; ls[qq] = 0.f;
        #pragma unroll
        for (int c = 0; c < 4; ++c) acc[qq][c] = 0.f;
    }
    const float scale = 0.088388347648318447f;

    for (int j0 = 0; j0 < nT; j0 += 32) {
        int jn = min(32, nT - j0);
        __syncthreads();
        for (int idx = tid; idx < 32*128; idx += 256) {
            int j = idx >> 7, d = idx & 127;
            float kv = 0.f, vv = 0.f;
            if (j < jn) {
                const float* kr = g_qkv + (size_t)(b*Sn + j0 + j)*(3*Dn) + Dn + h*DHn;
                kv = kr[d];
                vv = kr[Dn + d];
            }
            Ks[d][j] = kv;
            Vs[j][d] = vv;
        }
        __syncthreads();

        float s[4] = {0.f, 0.f, 0.f, 0.f};
#pragma unroll 4
        for (int d = 0; d < 128; ++d) {
            float kv = Ks[d][lane];
            #pragma unroll
            for (int qq = 0; qq < 4; ++qq) s[qq] += Qs[warp + 8*qq][d] * kv;
        }
        float p[4], cr[4];
        #pragma unroll
        for (int qq = 0; qq < 4; ++qq) {
            float sq = s[qq] * scale;
            if (lane >= jn) sq = -1e30f;
            float sm = sq;
            #pragma unroll
            for (int off = 16; off; off >>= 1)
                sm = fmaxf(sm, __shfl_xor_sync(0xffffffffu, sm, off));
            float mn = fmaxf(mx[qq], sm);
            p[qq] = (lane < jn) ? __expf(sq - mn) : 0.f;
            float ps = p[qq];
            #pragma unroll
            for (int off = 16; off; off >>= 1)
                ps += __shfl_xor_sync(0xffffffffu, ps, off);
            cr[qq] = __expf(mx[qq] - mn);
            ls[qq] = ls[qq] * cr[qq] + ps;
            mx[qq] = mn;
        }
        #pragma unroll
        for (int qq = 0; qq < 4; ++qq)
            #pragma unroll
            for (int c = 0; c < 4; ++c) acc[qq][c] *= cr[qq];
        for (int j = 0; j < jn; ++j) {
            float pj[4];
            #pragma unroll
            for (int qq = 0; qq < 4; ++qq)
                pj[qq] = __shfl_sync(0xffffffffu, p[qq], j);
            #pragma unroll
            for (int c = 0; c < 4; ++c) {
                float vv = Vs[j][lane + 32*c];
                #pragma unroll
                for (int qq = 0; qq < 4; ++qq) acc[qq][c] += pj[qq] * vv;
            }
        }
    }
    #pragma unroll
    for (int qq = 0; qq < 4; ++qq) {
        if (qv[qq]) {
            float inv = 1.f / ls[qq];
            size_t rb = (size_t)(b*Sn + qb[qq]) * Dn + h * DHn;
            #pragma unroll
            for (int c = 0; c < 4; ++c)
                g_ctx_h[rb + lane + 32*c] = __float2half_rn(acc[qq][c] * inv);
        }
    }
}

// ---------------- block reduction helper ------------------------------------------
__device__ __forceinline__ float block_sum256(float v, float* red)
{
    int lane = threadIdx.x & 31, warp = threadIdx.x >> 5;
#pragma unroll
    for (int off = 16; off; off >>= 1) v += __shfl_xor_sync(0xffffffffu, v, off);
    if (lane == 0) red[warp] = v;
    __syncthreads();
    if (warp == 0) {
        float t = (lane < 8) ? red[lane] : 0.f;
#pragma unroll
        for (int off = 4; off; off >>= 1) t += __shfl_xor_sync(0xffffffffu, t, off);
        if (lane == 0) red[0] = t;
    }
    __syncthreads();
    float r = red[0];
    __syncthreads();
    return r;
}

// ---------------- fused residual-add + LayerNorm (per-batch via roff) -------------
__global__ void __launch_bounds__(256) add_ln_kernel(
    const float* __restrict__ X, const float* __restrict__ Y,
    const float* __restrict__ g, const float* __restrict__ be,
    float* __restrict__ out, __half* __restrict__ oh, int use_cnt, int roff)
{
    int r = blockIdx.x + roff;
    if (use_cnt) { int b = r >> 11; if ((r & 2047) >= g_tcnt[b]) return; }
    __shared__ float red[8];
    int t = threadIdx.x;
    float4 xv = ((const float4*)(X + (size_t)r * Dn))[t];
    float4 yv = ((const float4*)(Y + (size_t)r * Dn))[t];
    float v0 = xv.x + yv.x, v1 = xv.y + yv.y, v2 = xv.z + yv.z, v3 = xv.w + yv.w;
    float mu = block_sum256(v0 + v1 + v2 + v3, red) * (1.0f / Dn);
    float d0 = v0 - mu, d1 = v1 - mu, d2 = v2 - mu, d3 = v3 - mu;
    float var = block_sum256(d0*d0 + d1*d1 + d2*d2 + d3*d3, red) * (1.0f / Dn);
    float inv = rsqrtf(var + 1e-5f);
    float4 gv = ((const float4*)g)[t];
    float4 bv = ((const float4*)be)[t];
    float4 o;
    o.x = d0 * inv * gv.x + bv.x;
    o.y = d1 * inv * gv.y + bv.y;
    o.z = d2 * inv * gv.z + bv.z;
    o.w = d3 * inv * gv.w + bv.w;
    ((float4*)(out + (size_t)r * Dn))[t] = o;
    if (oh) ((uint2*)(oh + (size_t)r * Dn))[t] = cvt4h(o);
}

// ---------------- cat init: cat = [x | x] (fp16), eff = 0.1 ------------------------
__global__ void init_cat_kernel(const float* __restrict__ x)
{
    int r = blockIdx.x, t = threadIdx.x;
    float4 v = ((const float4*)(x + (size_t)r * Dn))[t];
    uint2 h = cvt4h(v);
    uint2* ch = (uint2*)(g_cat_h + (size_t)r * 2 * Dn);
    ch[t] = h; ch[t + 256] = h;
    if (t == 0) g_eff[r] = 0.1f;
}

// ---------------- scatter x2 into cat[:, D:] (fp16) + gate (per batch) ------------
__global__ void __launch_bounds__(256) scatter_kernel(
    const float* __restrict__ Wg, const float* __restrict__ bg, int b)
{
    int i = blockIdx.x;
    if (i >= g_tcnt[b]) return;
    __shared__ float red[8];
    int dst = b * Sn + g_tidx[b * Sn + i];
    int t = threadIdx.x;
    float4 v = ((const float4*)(g_x2 + (size_t)(b*Sn + i) * Dn))[t];
    ((uint2*)(g_cat_h + (size_t)dst * 2 * Dn + Dn))[t] = cvt4h(v);
    float4 w = ((const float4*)Wg)[t];
    float p = v.x*w.x + v.y*w.y + v.z*w.z + v.w*w.w;
    float tot = block_sum256(p, red);
    if (t == 0) g_eff[dst] = 1.f / (1.f + __expf(-(tot + bg[0])));
}

// ---------------- launch ------------------------------------------------------------
#define SYM(p, s) cudaGetSymbolAddress((void**)&p, s)

extern "C" void kernel_launch(void* const* d_in, const int* in_sizes, int n_in,
                              void* d_out, int out_size)
{
    const float* x    = (const float*)d_in[0];
    const int*   ids  = (const int*)d_in[1];
    const int*   sot  = (const int*)d_in[2];
    const int*   eot  = (const int*)d_in[3];
    const float* Wqkv = (const float*)d_in[4];
    const float* bqkv = (const float*)d_in[5];
    const float* Wo   = (const float*)d_in[6];
    const float* bo   = (const float*)d_in[7];
    const float* ln1g = (const float*)d_in[8];
    const float* ln1b = (const float*)d_in[9];
    const float* W1   = (const float*)d_in[10];
    const float* b1   = (const float*)d_in[11];
    const float* W2   = (const float*)d_in[12];
    const float* b2   = (const float*)d_in[13];
    const float* ln2g = (const float*)d_in[14];
    const float* ln2b = (const float*)d_in[15];
    const float* Wg   = (const float*)d_in[16];
    const float* bg   = (const float*)d_in[17];
    const float* Wm   = (const float*)d_in[18];
    const float* bm   = (const float*)d_in[19];
    const float* Wout = (const float*)d_in[20];
    const float* bout = (const float*)d_in[21];
    float* out = (float*)d_out;

    float *pXc, *pqkv, *pattno, *px1, *pff, *px2;
    __half *pXch, *pctxh, *px1h, *phffh, *pcath, *pmixh;
    __half *pWqkvh, *pWoh, *pW1h, *pW2h, *pWmh, *pWouth;
    SYM(pXc, g_Xc); SYM(pqkv, g_qkv); SYM(pattno, g_attno); SYM(px1, g_x1);
    SYM(pff, g_ff); SYM(px2, g_x2);
    SYM(pXch, g_Xc_h); SYM(pctxh, g_ctx_h); SYM(px1h, g_x1_h); SYM(phffh, g_hff_h);
    SYM(pcath, g_cat_h); SYM(pmixh, g_mix_h);
    SYM(pWqkvh, g_Wqkv_h); SYM(pWoh, g_Wo_h); SYM(pW1h, g_W1_h); SYM(pW2h, g_W2_h);
    SYM(pWmh, g_Wm_h); SYM(pWouth, g_Wout_h);

    cudaFuncSetAttribute(gemm_hs<false,false,false>, cudaFuncAttributeMaxDynamicSharedMemorySize, GSMEM);
    cudaFuncSetAttribute(gemm_hs<true,true,false>,   cudaFuncAttributeMaxDynamicSharedMemorySize, GSMEM);
    cudaFuncSetAttribute(gemm_hs<false,false,true>,  cudaFuncAttributeMaxDynamicSharedMemorySize, GSMEM);

    // one-time stream/event setup (host-side objects; no device allocations)
    static cudaStream_t s1 = nullptr, s2 = nullptr;
    static cudaEvent_t evF = nullptr, evW = nullptr, evR = nullptr, evG = nullptr, evD = nullptr;
    if (!s1) {
        cudaStreamCreateWithFlags(&s1, cudaStreamNonBlocking);
        cudaStreamCreateWithFlags(&s2, cudaStreamNonBlocking);
        cudaEventCreateWithFlags(&evF, cudaEventDisableTiming);
        cudaEventCreateWithFlags(&evW, cudaEventDisableTiming);
        cudaEventCreateWithFlags(&evR, cudaEventDisableTiming);
        cudaEventCreateWithFlags(&evG, cudaEventDisableTiming);
        cudaEventCreateWithFlags(&evD, cudaEventDisableTiming);
    }

    // tail of the per-batch chain: everything from Wo onward (needs all weights + init_cat)
    auto chain_tail = [&](cudaStream_t st, int b) {
        int mo = 16 * b;
        gemm_hs<false,false,false><<<16*8, 256, GSMEM, st>>>(pctxh, pWoh, bo, pattno, nullptr, nullptr, Dn, Dn, 1, 4, mo);
        add_ln_kernel<<<Sn, 256, 0, st>>>(pXc, pattno, ln1g, ln1b, px1, px1h, 1, b*Sn);
        gemm_hs<true,true,false><<<16*32, 256, GSMEM, st>>>(px1h, pW1h, b1, nullptr, phffh, nullptr, DFFn, Dn, 1, 4, mo);
        gemm_hs<false,false,false><<<16*8, 256, GSMEM, st>>>(phffh, pW2h, b2, pff, nullptr, nullptr, Dn, DFFn, 1, 4, mo);
        add_ln_kernel<<<Sn, 256, 0, st>>>(px1, pff, ln2g, ln2b, px2, nullptr, 1, b*Sn);
        scatter_kernel<<<Sn, 256, 0, st>>>(Wg, bg, b);
        gemm_hs<false,false,true><<<16*8, 256, GSMEM, st>>>(pcath, pWmh, bm, nullptr, pmixh, x, Dn, 2*Dn, 0, 4, mo);
        gemm_hs<false,false,false><<<16*250, 256, GSMEM, st>>>(pmixh, pWouth, bout, out, nullptr, nullptr, Vn, Dn, 0, 4, mo);
    };

    // ---- fork ----
    cudaEventRecord(evF, 0);
    cudaStreamWaitEvent(s1, evF, 0);
    cudaStreamWaitEvent(s2, evF, 0);

    // ---- s2: weight conversions + init_cat (dedicated stream, never blocked) ----
    conv_kernel<<<512, 256, 0, s2>>>((const float4*)Wqkv, (uint2*)pWqkvh, 3*Dn*Dn/4);
    cudaEventRecord(evW, s2);   // Wqkv ready — both QKV GEMMs can start
    conv_kernel<<<256, 256, 0, s2>>>((const float4*)Wo,   (uint2*)pWoh,   Dn*Dn/4);
    conv_kernel<<<512, 256, 0, s2>>>((const float4*)W1,   (uint2*)pW1h,   DFFn*Dn/4);
    conv_kernel<<<512, 256, 0, s2>>>((const float4*)W2,   (uint2*)pW2h,   Dn*DFFn/4);
    conv_kernel<<<512, 256, 0, s2>>>((const float4*)Wm,   (uint2*)pWmh,   Dn*2*Dn/4);
    conv_kernel<<<2048, 256, 0, s2>>>((const float4*)Wout,(uint2*)pWouth, Vn*Dn/4);
    init_cat_kernel<<<Rn, 256, 0, s2>>>(x);
    cudaEventRecord(evR, s2);   // all weights + init_cat ready

    // ---- stream 0: mask + gather ----
    mask_kernel<<<Bn, 32>>>(ids, sot, eot);
    gather_kernel<<<dim3(Sn, Bn), 256>>>(x);
    cudaEventRecord(evG, 0);

    // ---- s1: batch-1 chain (starts right after gather + Wqkv conv) ----
    cudaStreamWaitEvent(s1, evG, 0);
    cudaStreamWaitEvent(s1, evW, 0);
    gemm_hs<false,false,false><<<16*24, 256, GSMEM, s1>>>(pXch, pWqkvh, bqkv, pqkv, nullptr, nullptr, 3*Dn, Dn, 1, 4, 16);
    attn_kernel<<<dim3(Sn/32, NHEADS), 256, 0, s1>>>(1);
    cudaStreamWaitEvent(s1, evR, 0);   // join remaining convs + init_cat
    chain_tail(s1, 1);
    cudaEventRecord(evD, s1);

    // ---- stream 0: batch-0 chain (symmetric) ----
    cudaStreamWaitEvent(0, evW, 0);
    gemm_hs<false,false,false><<<16*24, 256, GSMEM>>>(pXch, pWqkvh, bqkv, pqkv, nullptr, nullptr, 3*Dn, Dn, 1, 4, 0);
    attn_kernel<<<dim3(Sn/32, NHEADS), 256>>>(0);
    cudaStreamWaitEvent(0, evR, 0);    // join remaining convs + init_cat
    chain_tail(0, 0);
    cudaStreamWaitEvent(0, evD, 0);    // join batch-1 chain

    (void)in_sizes; (void)n_in; (void)out_size;
}